// round 4
// baseline (speedup 1.0000x reference)
#include <cuda_runtime.h>
#include <cstdint>

#define BB 128
#define NN 16384
#define KK 32
#define TPB_B 256
#define CHUNK 1024
#define CHUNKS_PER_ROW (NN / CHUNK)   // 16 (kernel B)

#define NCH 8                          // stats chunks per row
#define CHN (NN / NCH)                 // 2048 elems per stats chunk
#define TPB_S 256
#define NBINS 4096                     // 12-bit histogram
#define BPT (NBINS / TPB_S)            // 16 bins per thread
#define CAPC 256                       // per-chunk candidate cap (needs ~45)

// eps = FLT_EPSILON = 2^-23 ; eps^2 = 2^-46 ; 1/eps^2 = 2^46 (exact powers of 2)
#define EPSf    1.1920929e-07f
#define E2f     1.4210854715202004e-14f
#define INV_E2f 7.0368744177664e13f

// Scratch (allocation-free rule: __device__ globals)
__device__ float    g_t[BB * KK];            // top-k values, sorted descending
__device__ float    g_c[BB * KK];            // 1 - x_m_sum
__device__ float    g_cand[BB * NCH * CAPC]; // per-chunk candidates (1 MB)
__device__ unsigned g_cnt[BB * NCH];         // per-chunk candidate counts

__device__ __forceinline__ unsigned key_of(float f) {
    unsigned u = __float_as_uint(f);
    return (u & 0x80000000u) ? ~u : (u | 0x80000000u);
}
__device__ __forceinline__ float key_to_float(unsigned k) {
    unsigned u = (k & 0x80000000u) ? (k & 0x7FFFFFFFu) : ~k;
    return __uint_as_float(u);
}

// ---------------------------------------------------------------------------
// A1: per-chunk candidate collection. 1024 CTAs (8 per row), 256 threads.
// Local 12-bit histogram -> bin of the chunk's 32nd-largest -> collect all
// x >= binlo - 2eps (superset of chunk top-32 AND of any global contributor
// living in this chunk, since t_min_global >= t_min_chunk >= binlo).
// ---------------------------------------------------------------------------
__global__ void __launch_bounds__(TPB_S) chunk_cand_kernel(const float* __restrict__ x) {
    __shared__ unsigned hist[NBINS];    // 16 KB
    __shared__ unsigned csum[TPB_S];
    __shared__ unsigned s_cnt;
    __shared__ int s_bin;

    const int cid = blockIdx.x;         // row*8 + chunk
    const int tid = threadIdx.x;
    const float4* xr = (const float4*)(x) + (size_t)cid * (CHN / 4);

    for (int i = tid; i < NBINS; i += TPB_S) hist[i] = 0;
    if (tid == 0) s_cnt = 0;
    __syncthreads();

    // Load this thread's 8 values (2 float4, coalesced), histogram them.
    const float4 v0 = xr[tid];
    const float4 v1 = xr[tid + TPB_S];
    float vals[8] = {v0.x, v0.y, v0.z, v0.w, v1.x, v1.y, v1.z, v1.w};
    unsigned keys[8];
    #pragma unroll
    for (int c = 0; c < 8; c++) {
        keys[c] = key_of(vals[c]);
        unsigned dg = keys[c] >> 20;
        unsigned peers = __match_any_sync(0xFFFFFFFFu, dg);
        if ((int)(tid & 31) == __ffs(peers) - 1)
            atomicAdd(&hist[dg], (unsigned)__popc(peers));
    }
    __syncthreads();

    // Per-thread 16-bin sums, then parallel suffix-inclusive scan (256 wide).
    {
        unsigned s = 0;
        #pragma unroll
        for (int j = 0; j < BPT; j++) s += hist[tid * BPT + j];
        csum[tid] = s;
        __syncthreads();
        #pragma unroll
        for (int off = 1; off < TPB_S; off <<= 1) {
            unsigned t = (tid + off < TPB_S) ? csum[tid + off] : 0u;
            __syncthreads();
            csum[tid] += t;
            __syncthreads();
        }
    }
    // Unique thread whose 16-bin chunk crosses cum>=KK locates the exact bin.
    {
        unsigned incl = csum[tid];
        unsigned excl = (tid < TPB_S - 1) ? csum[tid + 1] : 0u;
        if (incl >= KK && excl < KK) {
            unsigned cum = excl;
            #pragma unroll
            for (int j = BPT - 1; j >= 0; j--) {
                cum += hist[tid * BPT + j];
                if (cum >= KK) { s_bin = tid * BPT + j; break; }
            }
        }
    }
    __syncthreads();

    // Collect candidates: key >= key(binlo - 2eps). (When |binlo| is large
    // enough that -2eps is absorbed, ulp(binlo) > eps, so nothing below binlo
    // can be inside an eps-window anyway -> threshold remains a superset.)
    const float binlo   = key_to_float((unsigned)s_bin << 20);
    const unsigned thrk = key_of(binlo - 2.0f * EPSf);
    float* my_cand = g_cand + (size_t)cid * CAPC;
    #pragma unroll
    for (int c = 0; c < 8; c++) {
        if (keys[c] >= thrk) {
            unsigned p = atomicAdd(&s_cnt, 1u);
            if (p < CAPC) my_cand[p] = vals[c];
        }
    }
    __syncthreads();
    if (tid == 0) g_cnt[cid] = min(s_cnt, (unsigned)CAPC);
}

// ---------------------------------------------------------------------------
// A2: per-row merge. 128 CTAs, 256 threads. Compact ~320 candidates,
// rank-select exact top-32 descending, compute 1 - x_m_sum.
// ---------------------------------------------------------------------------
__global__ void __launch_bounds__(TPB_S) merge_stats_kernel() {
    __shared__ float cand[NCH * CAPC];  // 8 KB
    __shared__ unsigned off[NCH + 1];
    __shared__ float st[KK];

    const int b   = blockIdx.x;
    const int tid = threadIdx.x;

    if (tid == 0) {
        unsigned o = 0;
        #pragma unroll
        for (int c = 0; c < NCH; c++) { off[c] = o; o += g_cnt[b * NCH + c]; }
        off[NCH] = o;
    }
    __syncthreads();
    const int m = (int)off[NCH];

    #pragma unroll
    for (int c = 0; c < NCH; c++) {
        const unsigned cnt = off[c + 1] - off[c];
        const float* src = g_cand + (size_t)(b * NCH + c) * CAPC;
        for (unsigned i = tid; i < cnt; i += TPB_S) cand[off[c] + i] = src[i];
    }
    __syncthreads();

    // Rank-select top-32 (descending) among m candidates.
    for (int i0 = tid; i0 < m; i0 += TPB_S) {
        unsigned kv = key_of(cand[i0]);
        int rank = 0;
        for (int i = 0; i < m; i++) {
            unsigned kw = key_of(cand[i]);
            rank += (kw > kv) || (kw == kv && i < i0);
        }
        if (rank < KK) st[rank] = cand[i0];
    }
    __syncthreads();

    if (tid < KK) {
        const float tj = st[tid];
        float acc = 0.f;
        for (int i = 0; i < m; i++) {
            float d = cand[i] - tj;
            acc += fmaxf(__fmaf_rn(-d, d, E2f), 0.f) * INV_E2f;
        }
        g_t[b * KK + tid] = tj;
        g_c[b * KK + tid] = 1.0f - acc;
    }
}

// ---------------------------------------------------------------------------
// Kernel B: streaming output writer (fastest measured variant, unchanged).
// 2048 CTAs x 256 threads; each thread owns 4 consecutive j's -> STG.128.
// ---------------------------------------------------------------------------
__global__ void __launch_bounds__(TPB_B) out_kernel(const float* __restrict__ x,
                                                    float* __restrict__ out) {
    __shared__ float sx[CHUNK];
    __shared__ float st[KK], sc[KK];

    const int cid = blockIdx.x;
    const int b   = cid >> 4;                 // CHUNKS_PER_ROW == 16
    const int n0  = (cid & 15) * CHUNK;
    const int tid = threadIdx.x;

    if (tid < KK) { st[tid] = g_t[b * KK + tid]; sc[tid] = g_c[b * KK + tid]; }
    const float4* xv = (const float4*)(x + (size_t)b * NN + n0);
    for (int i = tid; i < CHUNK / 4; i += TPB_B) ((float4*)sx)[i] = xv[i];
    __syncthreads();

    const int q  = tid & 7;                   // quad index: j = 4q..4q+3
    const int nt = tid >> 3;                  // n-offset within group of 32
    const int j0 = q * 4;
    const float t0 = st[j0 + 0], t1 = st[j0 + 1], t2 = st[j0 + 2], t3 = st[j0 + 3];
    const float c0 = sc[j0 + 0], c1 = sc[j0 + 1], c2 = sc[j0 + 2], c3 = sc[j0 + 3];

    float4* ov = (float4*)(out + ((size_t)b * NN + n0) * KK);

    #pragma unroll 4
    for (int i = nt; i < CHUNK; i += TPB_B / 8) {
        const float xl = sx[i];
        float d;
        float4 r;
        d = xl - t0; r.x = fmaxf(__fmaf_rn(fmaxf(__fmaf_rn(-d, d, E2f), 0.f), INV_E2f, c0), 0.f);
        d = xl - t1; r.y = fmaxf(__fmaf_rn(fmaxf(__fmaf_rn(-d, d, E2f), 0.f), INV_E2f, c1), 0.f);
        d = xl - t2; r.z = fmaxf(__fmaf_rn(fmaxf(__fmaf_rn(-d, d, E2f), 0.f), INV_E2f, c2), 0.f);
        d = xl - t3; r.w = fmaxf(__fmaf_rn(fmaxf(__fmaf_rn(-d, d, E2f), 0.f), INV_E2f, c3), 0.f);
        __stcs(&ov[(size_t)i * 8 + q], r);    // streaming store: output is write-once
    }
}

// ---------------------------------------------------------------------------
extern "C" void kernel_launch(void* const* d_in, const int* in_sizes, int n_in,
                              void* d_out, int out_size) {
    const float* x = (const float*)d_in[0];
    float* out = (float*)d_out;
    (void)in_sizes; (void)n_in; (void)out_size;   // shapes fixed: (128,16384), k=32

    chunk_cand_kernel<<<BB * NCH, TPB_S>>>(x);
    merge_stats_kernel<<<BB, TPB_S>>>();
    out_kernel<<<BB * CHUNKS_PER_ROW, TPB_B>>>(x, out);
}

// round 5
// speedup vs baseline: 1.6304x; 1.6304x over previous
#include <cuda_runtime.h>
#include <cstdint>

#define BB 128
#define NN 16384
#define KK 32
#define TPB_A 1024
#define TPB_B 256
#define CHUNK 1024
#define CHUNKS_PER_ROW (NN / CHUNK)   // 16
#define CAP 8192                       // candidate cap (32 KB smem)
#define THR 2.5f                       // fast-path threshold (bench: ~100 hits/row)
#define NBINS 4096                     // fallback histogram
#define NCHUNK (NBINS / 8)             // 512

// eps = FLT_EPSILON = 2^-23 ; eps^2 = 2^-46 ; 1/eps^2 = 2^46 (exact powers of 2)
#define EPSf    1.1920929e-07f
#define E2f     1.4210854715202004e-14f
#define INV_E2f 7.0368744177664e13f

__device__ float g_t[BB * KK];   // top-k values, sorted descending
__device__ float g_c[BB * KK];   // 1 - x_m_sum

__device__ __forceinline__ unsigned key_of(float f) {
    unsigned u = __float_as_uint(f);
    return (u & 0x80000000u) ? ~u : (u | 0x80000000u);
}
__device__ __forceinline__ float key_to_float(unsigned k) {
    unsigned u = (k & 0x80000000u) ? (k & 0x7FFFFFFFu) : ~k;
    return __uint_as_float(u);
}

// ---------------------------------------------------------------------------
// Kernel A v5: one CTA per row, 1024 threads, row held in registers.
// Fast path: collect x >= THR (superset of exact top-32 and of all
// eps-window contributors, since ulp(THR) > eps at |THR| >= 2).
// Fallback (never taken on bench data, keeps exactness for any input):
// round-3 12-bit histogram select.
// ---------------------------------------------------------------------------
__global__ void __launch_bounds__(TPB_A) topk_stats_kernel(const float* __restrict__ x) {
    extern __shared__ unsigned char smem_raw[];
    float*    cand = (float*)smem_raw;                     // 32 KB
    unsigned* hist = (unsigned*)(smem_raw + CAP * 4);      // 16 KB (fallback only)
    __shared__ unsigned csum[NCHUNK];                      // 2 KB  (fallback only)
    __shared__ float st[KK];
    __shared__ unsigned s_cnt;
    __shared__ int s_bin;

    const int b   = blockIdx.x;
    const int tid = threadIdx.x;
    const float4* xr = (const float4*)(x + (size_t)b * NN);

    if (tid == 0) s_cnt = 0;
    __syncthreads();

    // Load this thread's 16 values (4 coalesced float4).
    float4 v0 = xr[tid];
    float4 v1 = xr[tid + TPB_A];
    float4 v2 = xr[tid + 2 * TPB_A];
    float4 v3 = xr[tid + 3 * TPB_A];
    float vals[16] = {v0.x, v0.y, v0.z, v0.w, v1.x, v1.y, v1.z, v1.w,
                      v2.x, v2.y, v2.z, v2.w, v3.x, v3.y, v3.z, v3.w};

    // ---- Fast path: threshold collect ----
    #pragma unroll
    for (int c = 0; c < 16; c++) {
        if (vals[c] >= THR) {
            unsigned p = atomicAdd(&s_cnt, 1u);
            if (p < CAP) cand[p] = vals[c];
        }
    }
    __syncthreads();
    unsigned cnt = s_cnt;

    if (cnt < KK || cnt > CAP) {
        // ---- Fallback: exact 12-bit histogram select (round-3 logic) ----
        for (int i = tid; i < NBINS; i += TPB_A) hist[i] = 0;
        __syncthreads();
        #pragma unroll
        for (int c = 0; c < 16; c++) {
            unsigned dg = key_of(vals[c]) >> 20;
            unsigned peers = __match_any_sync(0xFFFFFFFFu, dg);
            if ((int)(tid & 31) == __ffs(peers) - 1)
                atomicAdd(&hist[dg], (unsigned)__popc(peers));
        }
        __syncthreads();
        if (tid < NCHUNK) {
            unsigned s = 0;
            #pragma unroll
            for (int j = 0; j < 8; j++) s += hist[tid * 8 + j];
            csum[tid] = s;
        }
        __syncthreads();
        for (int off = 1; off < NCHUNK; off <<= 1) {
            unsigned t = (tid < NCHUNK && tid + off < NCHUNK) ? csum[tid + off] : 0u;
            __syncthreads();
            if (tid < NCHUNK) csum[tid] += t;
            __syncthreads();
        }
        if (tid < NCHUNK) {
            unsigned incl = csum[tid];
            unsigned excl = (tid < NCHUNK - 1) ? csum[tid + 1] : 0u;
            if (incl >= KK && excl < KK) {
                unsigned cum = excl;
                #pragma unroll
                for (int j = 7; j >= 0; j--) {
                    cum += hist[tid * 8 + j];
                    if (cum >= KK) { s_bin = tid * 8 + j; break; }
                }
            }
        }
        __syncthreads();
        const float binlo   = key_to_float((unsigned)s_bin << 20);
        const unsigned thrk = key_of(binlo - 2.0f * EPSf);
        if (tid == 0) s_cnt = 0;
        __syncthreads();
        #pragma unroll
        for (int c = 0; c < 16; c++) {
            if (key_of(vals[c]) >= thrk) {
                unsigned p = atomicAdd(&s_cnt, 1u);
                if (p < CAP) cand[p] = vals[c];
            }
        }
        __syncthreads();
        cnt = min(s_cnt, (unsigned)CAP);
    }
    const int m = (int)cnt;

    // ---- Rank-select top-32 (descending) among m candidates ----
    for (int i0 = tid; i0 < m; i0 += TPB_A) {
        unsigned kv = key_of(cand[i0]);
        int rank = 0;
        for (int i = 0; i < m; i++) {
            unsigned kw = key_of(cand[i]);
            rank += (kw > kv) || (kw == kv && i < i0);
        }
        if (rank < KK) st[rank] = cand[i0];
    }
    __syncthreads();

    // ---- 1 - x_m_sum_j over candidates only ----
    if (tid < KK) {
        const float tj = st[tid];
        float acc = 0.f;
        for (int i = 0; i < m; i++) {
            float d = cand[i] - tj;
            acc += fmaxf(__fmaf_rn(-d, d, E2f), 0.f) * INV_E2f;
        }
        g_t[b * KK + tid] = tj;
        g_c[b * KK + tid] = 1.0f - acc;
    }
}

// ---------------------------------------------------------------------------
// Kernel B: streaming output writer (fastest measured variant, unchanged).
// 2048 CTAs x 256 threads; each thread owns 4 consecutive j's -> STG.128.
// ---------------------------------------------------------------------------
__global__ void __launch_bounds__(TPB_B) out_kernel(const float* __restrict__ x,
                                                    float* __restrict__ out) {
    __shared__ float sx[CHUNK];
    __shared__ float st[KK], sc[KK];

    const int cid = blockIdx.x;
    const int b   = cid >> 4;                 // CHUNKS_PER_ROW == 16
    const int n0  = (cid & 15) * CHUNK;
    const int tid = threadIdx.x;

    if (tid < KK) { st[tid] = g_t[b * KK + tid]; sc[tid] = g_c[b * KK + tid]; }
    const float4* xv = (const float4*)(x + (size_t)b * NN + n0);
    for (int i = tid; i < CHUNK / 4; i += TPB_B) ((float4*)sx)[i] = xv[i];
    __syncthreads();

    const int q  = tid & 7;                   // quad index: j = 4q..4q+3
    const int nt = tid >> 3;                  // n-offset within group of 32
    const int j0 = q * 4;
    const float t0 = st[j0 + 0], t1 = st[j0 + 1], t2 = st[j0 + 2], t3 = st[j0 + 3];
    const float c0 = sc[j0 + 0], c1 = sc[j0 + 1], c2 = sc[j0 + 2], c3 = sc[j0 + 3];

    float4* ov = (float4*)(out + ((size_t)b * NN + n0) * KK);

    #pragma unroll 4
    for (int i = nt; i < CHUNK; i += TPB_B / 8) {
        const float xl = sx[i];
        float d;
        float4 r;
        d = xl - t0; r.x = fmaxf(__fmaf_rn(fmaxf(__fmaf_rn(-d, d, E2f), 0.f), INV_E2f, c0), 0.f);
        d = xl - t1; r.y = fmaxf(__fmaf_rn(fmaxf(__fmaf_rn(-d, d, E2f), 0.f), INV_E2f, c1), 0.f);
        d = xl - t2; r.z = fmaxf(__fmaf_rn(fmaxf(__fmaf_rn(-d, d, E2f), 0.f), INV_E2f, c2), 0.f);
        d = xl - t3; r.w = fmaxf(__fmaf_rn(fmaxf(__fmaf_rn(-d, d, E2f), 0.f), INV_E2f, c3), 0.f);
        __stcs(&ov[(size_t)i * 8 + q], r);    // streaming store: output is write-once
    }
}

// ---------------------------------------------------------------------------
extern "C" void kernel_launch(void* const* d_in, const int* in_sizes, int n_in,
                              void* d_out, int out_size) {
    const float* x = (const float*)d_in[0];
    float* out = (float*)d_out;
    (void)in_sizes; (void)n_in; (void)out_size;   // shapes fixed: (128,16384), k=32

    const int smem_a = CAP * 4 + NBINS * 4;       // 48 KB (cand | hist)
    cudaFuncSetAttribute(topk_stats_kernel,
                         cudaFuncAttributeMaxDynamicSharedMemorySize, smem_a);

    topk_stats_kernel<<<BB, TPB_A, smem_a>>>(x);
    out_kernel<<<BB * CHUNKS_PER_ROW, TPB_B>>>(x, out);
}

// round 6
// speedup vs baseline: 1.7112x; 1.0495x over previous
#include <cuda_runtime.h>
#include <cstdint>

#define BB 128
#define NN 16384
#define KK 32
#define TPB_A 1024
#define CAP 4096                       // candidate cap (bench needs ~100)
#define THR 2.5f                       // fast-path threshold
#define NBINS 4096                     // fallback histogram (aliases cidx smem)
#define NCHUNK (NBINS / 8)             // 512

// Zero-fill kernel shape: 4096 CTAs x 256 thr x 16 float4 = 256 MB
#define TPB_Z 256
#define ZF4_PER_T 16
#define ZGRID (BB * NN * KK / 4 / (TPB_Z * ZF4_PER_T))   // 4096

// eps = FLT_EPSILON = 2^-23 ; eps^2 = 2^-46 ; 1/eps^2 = 2^46 (exact powers of 2)
#define EPSf    1.1920929e-07f
#define E2f     1.4210854715202004e-14f
#define INV_E2f 7.0368744177664e13f

__device__ __forceinline__ unsigned key_of(float f) {
    unsigned u = __float_as_uint(f);
    return (u & 0x80000000u) ? ~u : (u | 0x80000000u);
}
__device__ __forceinline__ float key_to_float(unsigned k) {
    unsigned u = (k & 0x80000000u) ? (k & 0x7FFFFFFFu) : ~k;
    return __uint_as_float(u);
}

// ---------------------------------------------------------------------------
// zero_kernel: pure streaming zero-fill of the whole output (exact value for
// every non-candidate position, since s_j >= 1 always -> relu(1 - s_j) == 0).
// ---------------------------------------------------------------------------
__global__ void __launch_bounds__(TPB_Z) zero_kernel(float4* __restrict__ o) {
    const float4 z = make_float4(0.f, 0.f, 0.f, 0.f);
    float4* base = o + (size_t)blockIdx.x * (TPB_Z * ZF4_PER_T) + threadIdx.x;
    #pragma unroll
    for (int k = 0; k < ZF4_PER_T; k++)
        __stcs(base + k * TPB_Z, z);
}

// ---------------------------------------------------------------------------
// stats_scatter_kernel: one CTA per row, 1024 threads, row in registers.
// Fast path: collect (value, index) of all x >= THR — provable superset of the
// exact top-32 and of every eps-window contributor (ulp(THR) > eps).
// Fallback for arbitrary inputs: exact 12-bit histogram select.
// Then: rank-select top-32 descending, c_j = 1 - sum_i x_m(i,j) over
// candidates (exact: non-candidates contribute exactly 0), and scatter-write
// the full 32-wide output segment of each candidate row position.
// ---------------------------------------------------------------------------
__global__ void __launch_bounds__(TPB_A) stats_scatter_kernel(const float* __restrict__ x,
                                                              float* __restrict__ out) {
    extern __shared__ unsigned char smem_raw[];
    float*    cand = (float*)smem_raw;                     // 16 KB
    unsigned* cidx = (unsigned*)(smem_raw + CAP * 4);      // 16 KB (aliases hist)
    unsigned* hist = cidx;                                 // fallback-only, then clobbered
    __shared__ unsigned csum[NCHUNK];
    __shared__ float st[KK], sc[KK];
    __shared__ unsigned s_cnt;
    __shared__ int s_bin;

    const int b   = blockIdx.x;
    const int tid = threadIdx.x;
    const float4* xr = (const float4*)(x + (size_t)b * NN);

    if (tid == 0) s_cnt = 0;
    __syncthreads();

    // Load this thread's 16 values (4 coalesced float4) + their indices.
    float4 v0 = xr[tid];
    float4 v1 = xr[tid + TPB_A];
    float4 v2 = xr[tid + 2 * TPB_A];
    float4 v3 = xr[tid + 3 * TPB_A];
    float vals[16] = {v0.x, v0.y, v0.z, v0.w, v1.x, v1.y, v1.z, v1.w,
                      v2.x, v2.y, v2.z, v2.w, v3.x, v3.y, v3.z, v3.w};
    unsigned idxs[16];
    #pragma unroll
    for (int c = 0; c < 16; c++)
        idxs[c] = 4u * (unsigned)(tid + (c >> 2) * TPB_A) + (c & 3);

    // ---- Fast path: threshold collect (values + indices) ----
    #pragma unroll
    for (int c = 0; c < 16; c++) {
        if (vals[c] >= THR) {
            unsigned p = atomicAdd(&s_cnt, 1u);
            if (p < CAP) { cand[p] = vals[c]; cidx[p] = idxs[c]; }
        }
    }
    __syncthreads();
    unsigned cnt = s_cnt;

    if (cnt < KK || cnt > CAP) {
        // ---- Fallback: exact 12-bit histogram select ----
        for (int i = tid; i < NBINS; i += TPB_A) hist[i] = 0;
        __syncthreads();
        #pragma unroll
        for (int c = 0; c < 16; c++) {
            unsigned dg = key_of(vals[c]) >> 20;
            unsigned peers = __match_any_sync(0xFFFFFFFFu, dg);
            if ((int)(tid & 31) == __ffs(peers) - 1)
                atomicAdd(&hist[dg], (unsigned)__popc(peers));
        }
        __syncthreads();
        if (tid < NCHUNK) {
            unsigned s = 0;
            #pragma unroll
            for (int j = 0; j < 8; j++) s += hist[tid * 8 + j];
            csum[tid] = s;
        }
        __syncthreads();
        for (int off = 1; off < NCHUNK; off <<= 1) {
            unsigned t = (tid < NCHUNK && tid + off < NCHUNK) ? csum[tid + off] : 0u;
            __syncthreads();
            if (tid < NCHUNK) csum[tid] += t;
            __syncthreads();
        }
        if (tid < NCHUNK) {
            unsigned incl = csum[tid];
            unsigned excl = (tid < NCHUNK - 1) ? csum[tid + 1] : 0u;
            if (incl >= KK && excl < KK) {
                unsigned cum = excl;
                #pragma unroll
                for (int j = 7; j >= 0; j--) {
                    cum += hist[tid * 8 + j];
                    if (cum >= KK) { s_bin = tid * 8 + j; break; }
                }
            }
        }
        __syncthreads();
        const float binlo   = key_to_float((unsigned)s_bin << 20);
        const unsigned thrk = key_of(binlo - 2.0f * EPSf);
        if (tid == 0) s_cnt = 0;
        __syncthreads();        // hist no longer needed; cidx reuses its space
        #pragma unroll
        for (int c = 0; c < 16; c++) {
            if (key_of(vals[c]) >= thrk) {
                unsigned p = atomicAdd(&s_cnt, 1u);
                if (p < CAP) { cand[p] = vals[c]; cidx[p] = idxs[c]; }
            }
        }
        __syncthreads();
        cnt = min(s_cnt, (unsigned)CAP);
    }
    const int m = (int)cnt;

    // ---- Rank-select top-32 (descending) among m candidates ----
    for (int i0 = tid; i0 < m; i0 += TPB_A) {
        unsigned kv = key_of(cand[i0]);
        int rank = 0;
        for (int i = 0; i < m; i++) {
            unsigned kw = key_of(cand[i]);
            rank += (kw > kv) || (kw == kv && i < i0);
        }
        if (rank < KK) st[rank] = cand[i0];
    }
    __syncthreads();

    // ---- c_j = 1 - x_m_sum_j over candidates only (exact) ----
    if (tid < KK) {
        const float tj = st[tid];
        float acc = 0.f;
        for (int i = 0; i < m; i++) {
            float d = cand[i] - tj;
            acc += fmaxf(__fmaf_rn(-d, d, E2f), 0.f) * INV_E2f;
        }
        sc[tid] = 1.0f - acc;
    }
    __syncthreads();

    // ---- Scatter: write the 32-wide output segment of each candidate ----
    // (everything else is exactly zero, already written by zero_kernel)
    for (int w = tid; w < m * 8; w += TPB_A) {
        const int p = w >> 3, q = w & 7, j0 = q * 4;
        const float xv = cand[p];
        const unsigned i = cidx[p];
        float d;
        float4 r;
        d = xv - st[j0 + 0]; r.x = fmaxf(__fmaf_rn(fmaxf(__fmaf_rn(-d, d, E2f), 0.f), INV_E2f, sc[j0 + 0]), 0.f);
        d = xv - st[j0 + 1]; r.y = fmaxf(__fmaf_rn(fmaxf(__fmaf_rn(-d, d, E2f), 0.f), INV_E2f, sc[j0 + 1]), 0.f);
        d = xv - st[j0 + 2]; r.z = fmaxf(__fmaf_rn(fmaxf(__fmaf_rn(-d, d, E2f), 0.f), INV_E2f, sc[j0 + 2]), 0.f);
        d = xv - st[j0 + 3]; r.w = fmaxf(__fmaf_rn(fmaxf(__fmaf_rn(-d, d, E2f), 0.f), INV_E2f, sc[j0 + 3]), 0.f);
        float4* dst = (float4*)(out + ((size_t)b * NN + i) * KK);
        dst[q] = r;
    }
}

// ---------------------------------------------------------------------------
extern "C" void kernel_launch(void* const* d_in, const int* in_sizes, int n_in,
                              void* d_out, int out_size) {
    const float* x = (const float*)d_in[0];
    float* out = (float*)d_out;
    (void)in_sizes; (void)n_in; (void)out_size;   // shapes fixed: (128,16384), k=32

    const int smem_a = CAP * 4 + CAP * 4;         // 32 KB (cand | cidx/hist)
    cudaFuncSetAttribute(stats_scatter_kernel,
                         cudaFuncAttributeMaxDynamicSharedMemorySize, smem_a);

    zero_kernel<<<ZGRID, TPB_Z>>>((float4*)out);
    stats_scatter_kernel<<<BB, TPB_A, smem_a>>>(x, out);
}